// round 2
// baseline (speedup 1.0000x reference)
#include <cuda_runtime.h>
#include <math.h>

// Problem constants
#define NFFT     1024
#define HOP      256
#define SIGLEN   524288
#define NBATCH   32
#define GROUP    8            // output frames per CTA
#define NFRAMES  9            // FFT frames per CTA (GROUP+1)
#define NBINS    512          // output freq bins (k = 1..512)
#define THREADS  512
#define XBUFLEN  (GROUP*HOP + NFFT)   // 3072

__device__ __forceinline__ float wrap_pi(float d) {
    const float INV2PI = 0.15915494309189535f;
    const float TWOPI  = 6.283185307179586f;
    return d - TWOPI * rintf(d * INV2PI);
}

// radix-2 DIT stages on bit-reversed-loaded data in shared memory.
// 512 threads, one butterfly per thread per stage.
__device__ __forceinline__ void fft1024(float2* S, const float2* TW, int tid) {
    #pragma unroll
    for (int s = 0; s < 10; s++) {
        const int half = 1 << s;
        const int pos  = tid & (half - 1);
        const int i0   = ((tid >> s) << (s + 1)) | pos;
        const int i1   = i0 + half;
        const float2 w = TW[pos << (9 - s)];
        float2 a = S[i0];
        float2 b = S[i1];
        float tre = w.x * b.x - w.y * b.y;
        float tim = w.x * b.y + w.y * b.x;
        S[i0] = make_float2(a.x + tre, a.y + tim);
        S[i1] = make_float2(a.x - tre, a.y - tim);
        __syncthreads();
    }
}

extern __shared__ float smem_raw[];

__global__ __launch_bounds__(THREADS, 1)
void stft_kernel(const float* __restrict__ x, float* __restrict__ out)
{
    // ---- shared layout ----
    float2* S    = (float2*)smem_raw;            // 1024 * 8B  = 8192B
    float2* TW   = S + NFFT;                     // 512  * 8B  = 4096B
    float*  win  = (float*)(TW + 512);           // 1024 * 4B  = 4096B
    float*  xbuf = win + NFFT;                   // 3072 * 4B  = 12288B
    float*  ph   = xbuf + XBUFLEN;               // 9*512*4B   = 18432B
    float*  lm   = ph + NFRAMES * NBINS;         // 8*512*4B   = 16384B

    const int tid = threadIdx.x;
    const int grp = blockIdx.x;   // 0..255 (group of 8 output frames)
    const int b   = blockIdx.y;   // 0..31  (batch)

    // ---- twiddle table + hann window ----
    {
        // TW[p] = exp(-2*pi*i*p/1024), p in [0,512)
        float ang = -6.283185307179586f * (float)tid * (1.0f / 1024.0f);
        float sv, cv;
        sincosf(ang, &sv, &cv);
        TW[tid] = make_float2(cv, sv);
        #pragma unroll
        for (int n = tid; n < NFFT; n += THREADS)
            win[n] = 0.5f - 0.5f * cosf(6.283185307179586f * (float)n * (1.0f / 1024.0f));
    }

    // ---- load input window with reflect padding ----
    {
        const long base = (long)grp * (GROUP * HOP) - (NFFT / 2);
        const float* xb = x + (long)b * SIGLEN;
        #pragma unroll
        for (int i = tid; i < XBUFLEN; i += THREADS) {
            long p = base + i;
            if (p < 0) p = -p;
            else if (p >= SIGLEN) p = 2L * (SIGLEN - 1) - p;
            xbuf[i] = xb[p];
        }
    }
    __syncthreads();

    // ---- 5 complex FFTs covering 9 real frames (pairs packed in re/im) ----
    #pragma unroll
    for (int pr = 0; pr < 5; pr++) {
        const int gA = 2 * pr;
        const int gB = 2 * pr + 1;
        const bool hasB = (gB < NFRAMES);

        // windowed, bit-reverse-permuted load
        #pragma unroll
        for (int n = tid; n < NFFT; n += THREADS) {
            const float w  = win[n];
            const float re = w * xbuf[gA * HOP + n];
            const float im = hasB ? w * xbuf[gB * HOP + n] : 0.0f;
            const int   r  = __brev((unsigned)n) >> 22;
            S[r] = make_float2(re, im);
        }
        __syncthreads();

        fft1024(S, TW, tid);   // ends with __syncthreads

        // unpack spectra of the two packed real signals; k = tid+1 (skip DC)
        {
            const int k = tid + 1;
            const float2 Zk = S[k];
            const float2 Zr = S[NFFT - k];
            // A = spectrum of frame gA
            const float Are = 0.5f * (Zk.x + Zr.x);
            const float Aim = 0.5f * (Zk.y - Zr.y);
            ph[gA * NBINS + tid] = atan2f(Aim, Are);
            if (gA > 0) {
                const float m2 = Are * Are + Aim * Aim;
                lm[(gA - 1) * NBINS + tid] =
                    (0.5f * logf(fmaxf(m2, 1e-14f)) + 17.0f) * (1.0f / 23.0f);
            }
            if (hasB) {
                // B = spectrum of frame gB
                const float Bre = 0.5f * (Zk.y + Zr.y);
                const float Bim = 0.5f * (Zr.x - Zk.x);
                ph[gB * NBINS + tid] = atan2f(Bim, Bre);
                const float m2 = Bre * Bre + Bim * Bim;
                lm[(gB - 1) * NBINS + tid] =
                    (0.5f * logf(fmaxf(m2, 1e-14f)) + 17.0f) * (1.0f / 23.0f);
            }
        }
        __syncthreads();   // before S reuse
    }

    // ---- final coalesced writeout: thread tid owns freq row f=tid ----
    {
        const int f = tid;
        float m[GROUP], d[GROUP];
        #pragma unroll
        for (int j = 0; j < GROUP; j++) {
            m[j] = lm[j * NBINS + f];
            d[j] = wrap_pi(ph[(j + 1) * NBINS + f] - ph[j * NBINS + f]);
        }
        const long t0 = (long)grp * GROUP;
        float* o0 = out + ((((long)b * 2 + 0) * 512 + f) * 2048 + t0);
        float* o1 = out + ((((long)b * 2 + 1) * 512 + f) * 2048 + t0);
        ((float4*)o0)[0] = make_float4(m[0], m[1], m[2], m[3]);
        ((float4*)o0)[1] = make_float4(m[4], m[5], m[6], m[7]);
        ((float4*)o1)[0] = make_float4(d[0], d[1], d[2], d[3]);
        ((float4*)o1)[1] = make_float4(d[4], d[5], d[6], d[7]);
    }
}

extern "C" void kernel_launch(void* const* d_in, const int* in_sizes, int n_in,
                              void* d_out, int out_size)
{
    (void)in_sizes; (void)n_in; (void)out_size;
    const float* x = (const float*)d_in[0];
    float* out = (float*)d_out;

    const size_t shmem =
        NFFT * sizeof(float2) +          // S
        512  * sizeof(float2) +          // TW
        NFFT * sizeof(float)  +          // win
        XBUFLEN * sizeof(float) +        // xbuf
        NFRAMES * NBINS * sizeof(float) +// ph
        GROUP   * NBINS * sizeof(float); // lm

    cudaFuncSetAttribute(stft_kernel,
                         cudaFuncAttributeMaxDynamicSharedMemorySize,
                         (int)shmem);

    dim3 grid(2048 / GROUP, NBATCH);   // (256, 32)
    stft_kernel<<<grid, THREADS, shmem>>>(x, out);
}

// round 3
// speedup vs baseline: 2.0445x; 2.0445x over previous
#include <cuda_runtime.h>
#include <math.h>

// Problem constants
#define NFFT     1024
#define HOP      256
#define SIGLEN   524288
#define NBATCH   32
#define GROUP    8            // output frames per CTA
#define NFRAMES  9            // FFT frames per CTA (GROUP+1)
#define NBINS    512          // output freq bins (k = 1..512)
#define THREADS  512
#define XBUFLEN  (GROUP*HOP + NFFT)   // 3072

// precomputed tables (filled by init kernel, double-precision accurate)
__device__ float2 g_tw[NFFT];    // exp(-2*pi*i*t/1024)
__device__ float  g_win[NFFT];   // periodic hann

__global__ void init_tables()
{
    int t = blockIdx.x * blockDim.x + threadIdx.x;
    if (t < NFFT) {
        double ang = -2.0 * 3.14159265358979323846 * (double)t / 1024.0;
        double s, c;
        sincos(ang, &s, &c);
        g_tw[t] = make_float2((float)c, (float)s);
        g_win[t] = (float)(0.5 * (1.0 - cos(2.0 * 3.14159265358979323846 * (double)t / 1024.0)));
    }
}

__device__ __forceinline__ float wrap_pi(float d) {
    const float INV2PI = 0.15915494309189535f;
    const float TWOPI  = 6.283185307179586f;
    return d - TWOPI * rintf(d * INV2PI);
}

__device__ __forceinline__ float2 cmul(float2 a, float2 b) {
    return make_float2(a.x * b.x - a.y * b.y, a.x * b.y + a.y * b.x);
}

__device__ __forceinline__ float2 shflx(float2 v, int m) {
    float px = __shfl_xor_sync(0xffffffffu, v.x, m);
    float py = __shfl_xor_sync(0xffffffffu, v.y, m);
    return make_float2(px, py);
}

// 32-point DIF FFT across the 32 lanes of a warp.
// Input: lane l holds x[l]. Output: lane l holds X[brev5(l)].
// t16/t8/t4 are per-lane constant twiddles:
//   t16 = W32^(l&15), t8 = W16^(l&7), t4 = W8^(l&3)
__device__ __forceinline__ float2 wfft32(float2 v, int lane,
                                         float2 t16, float2 t8, float2 t4)
{
    float2 p;
    p = shflx(v, 16);
    if (lane & 16) v = cmul(make_float2(p.x - v.x, p.y - v.y), t16);
    else           v = make_float2(v.x + p.x, v.y + p.y);

    p = shflx(v, 8);
    if (lane & 8)  v = cmul(make_float2(p.x - v.x, p.y - v.y), t8);
    else           v = make_float2(v.x + p.x, v.y + p.y);

    p = shflx(v, 4);
    if (lane & 4)  v = cmul(make_float2(p.x - v.x, p.y - v.y), t4);
    else           v = make_float2(v.x + p.x, v.y + p.y);

    p = shflx(v, 2);
    if (lane & 2) {
        float2 s = make_float2(p.x - v.x, p.y - v.y);
        v = (lane & 1) ? make_float2(s.y, -s.x) : s;  // *(-i) when j==1
    } else {
        v = make_float2(v.x + p.x, v.y + p.y);
    }

    p = shflx(v, 1);
    if (lane & 1)  v = make_float2(p.x - v.x, p.y - v.y);
    else           v = make_float2(v.x + p.x, v.y + p.y);
    return v;
}

// padded index: +1 float per 32 (conflict-free for stride-32 access)
__device__ __forceinline__ int P(int i) { return i + (i >> 5); }

extern __shared__ float smem_raw[];

__global__ __launch_bounds__(THREADS, 2)
void stft_kernel(const float* __restrict__ x, float* __restrict__ out)
{
    // ---- shared layout (all float arrays) ----
    float* TWre  = smem_raw;                 // 1024
    float* TWim  = TWre + 1024;              // 1024
    float* winP  = TWim + 1024;              // 1056 (padded 1024)
    float* xbufP = winP + 1056;              // 3168 (padded 3072)
    float* Ysre  = xbufP + 3168;             // 32*33 = 1056
    float* Ysim  = Ysre + 1056;              // 1056
    float* Sre   = Ysim + 1056;              // 1056 (padded 1024)
    float* Sim   = Sre + 1056;               // 1056
    float* ph    = Sim + 1056;               // 9*512 = 4608
    float* lm    = ph + NFRAMES * NBINS;     // 8*512 = 4096
    // total 19200 floats = 76800 B

    const int tid  = threadIdx.x;
    const int w    = tid >> 5;
    const int lane = tid & 31;
    const int grp  = blockIdx.x;   // 0..255
    const int b    = blockIdx.y;   // 0..31

    // ---- stage tables from global (double-accurate) ----
    #pragma unroll
    for (int i = tid; i < NFFT; i += THREADS) {
        float2 t = g_tw[i];
        TWre[i] = t.x;
        TWim[i] = t.y;
        winP[P(i)] = g_win[i];
    }

    // per-lane warp-FFT twiddles (constant across all FFTs)
    const float2 t16 = g_tw[(lane & 15) << 5];
    const float2 t8  = g_tw[(lane & 7)  << 6];
    const float2 t4  = g_tw[(lane & 3)  << 7];
    const int    kk  = (int)(__brev((unsigned)lane) >> 27);  // brev5(lane)

    // ---- load input window with reflect padding (padded smem) ----
    {
        const long base = (long)grp * (GROUP * HOP) - (NFFT / 2);
        const float* xb = x + (long)b * SIGLEN;
        #pragma unroll
        for (int i = tid; i < XBUFLEN; i += THREADS) {
            long p = base + i;
            if (p < 0) p = -p;
            else if (p >= SIGLEN) p = 2L * (SIGLEN - 1) - p;
            xbufP[P(i)] = xb[p];
        }
    }
    __syncthreads();

    const int b0 = 2 * w;       // column / row indices owned by this warp
    const int b1 = 2 * w + 1;

    // ---- 5 complex FFTs covering 9 real frames (pairs packed in re/im) ----
    #pragma unroll
    for (int pr = 0; pr < 5; pr++) {
        const int gA = 2 * pr;
        const int gB = 2 * pr + 1;
        const bool hasB = (gB < NFRAMES);

        // ===== step 1: 32-pt FFT over a (lane dim) for columns b0, b1 =====
        // x[n], n = 32*a + b;  lane = a
        {
            const int n0 = (lane << 5) + b0;
            const int n1 = (lane << 5) + b1;
            const float w0 = winP[P(n0)];
            const float w1 = winP[P(n1)];
            float2 v0, v1;
            v0.x = w0 * xbufP[P(gA * HOP + n0)];
            v1.x = w1 * xbufP[P(gA * HOP + n1)];
            if (hasB) {
                v0.y = w0 * xbufP[P(gB * HOP + n0)];
                v1.y = w1 * xbufP[P(gB * HOP + n1)];
            } else {
                v0.y = 0.0f; v1.y = 0.0f;
            }

            v0 = wfft32(v0, lane, t16, t8, t4);   // Y[k1=kk, b0]
            v1 = wfft32(v1, lane, t16, t8, t4);   // Y[k1=kk, b1]

            // ===== step 2: twiddle W1024^(b*k1) =====
            {
                int tA = b0 * kk;                 // < 1024
                int tB = b1 * kk;
                v0 = cmul(v0, make_float2(TWre[tA], TWim[tA]));
                v1 = cmul(v1, make_float2(TWre[tB], TWim[tB]));
            }

            // transpose store (conflict-free: bank = (kk + b)%32)
            Ysre[kk * 33 + b0] = v0.x;  Ysim[kk * 33 + b0] = v0.y;
            Ysre[kk * 33 + b1] = v1.x;  Ysim[kk * 33 + b1] = v1.y;
        }
        __syncthreads();

        // ===== step 3: 32-pt FFT over b for rows k1 = b0, b1 =====
        {
            float2 u0 = make_float2(Ysre[b0 * 33 + lane], Ysim[b0 * 33 + lane]);
            float2 u1 = make_float2(Ysre[b1 * 33 + lane], Ysim[b1 * 33 + lane]);
            u0 = wfft32(u0, lane, t16, t8, t4);   // X[b0 + 32*kk]
            u1 = wfft32(u1, lane, t16, t8, t4);   // X[b1 + 32*kk]
            const int k0 = b0 + (kk << 5);
            const int k1i = b1 + (kk << 5);
            Sre[P(k0)] = u0.x;  Sim[P(k0)] = u0.y;
            Sre[P(k1i)] = u1.x; Sim[P(k1i)] = u1.y;
        }
        __syncthreads();

        // ===== unpack the two packed real spectra; k = tid+1 (skip DC) =====
        {
            const int k = tid + 1;
            const int r = NFFT - k;
            const float zkr = Sre[P(k)], zki = Sim[P(k)];
            const float zrr = Sre[P(r)], zri = Sim[P(r)];
            // A = spectrum of frame gA
            const float Are = 0.5f * (zkr + zrr);
            const float Aim = 0.5f * (zki - zri);
            ph[gA * NBINS + tid] = atan2f(Aim, Are);
            if (gA > 0) {
                const float m2 = Are * Are + Aim * Aim;
                lm[(gA - 1) * NBINS + tid] =
                    (0.5f * logf(fmaxf(m2, 1e-14f)) + 17.0f) * (1.0f / 23.0f);
            }
            if (hasB) {
                // B = spectrum of frame gB
                const float Bre = 0.5f * (zki + zri);
                const float Bim = 0.5f * (zrr - zkr);
                ph[gB * NBINS + tid] = atan2f(Bim, Bre);
                const float m2 = Bre * Bre + Bim * Bim;
                lm[(gB - 1) * NBINS + tid] =
                    (0.5f * logf(fmaxf(m2, 1e-14f)) + 17.0f) * (1.0f / 23.0f);
            }
        }
        __syncthreads();   // protect S (and Ys) before next iteration
    }

    // ---- final coalesced writeout: thread tid owns freq row f=tid ----
    {
        const int f = tid;
        float m[GROUP], d[GROUP];
        #pragma unroll
        for (int j = 0; j < GROUP; j++) {
            m[j] = lm[j * NBINS + f];
            d[j] = wrap_pi(ph[(j + 1) * NBINS + f] - ph[j * NBINS + f]);
        }
        const long t0 = (long)grp * GROUP;
        float* o0 = out + ((((long)b * 2 + 0) * 512 + f) * 2048 + t0);
        float* o1 = out + ((((long)b * 2 + 1) * 512 + f) * 2048 + t0);
        ((float4*)o0)[0] = make_float4(m[0], m[1], m[2], m[3]);
        ((float4*)o0)[1] = make_float4(m[4], m[5], m[6], m[7]);
        ((float4*)o1)[0] = make_float4(d[0], d[1], d[2], d[3]);
        ((float4*)o1)[1] = make_float4(d[4], d[5], d[6], d[7]);
    }
}

extern "C" void kernel_launch(void* const* d_in, const int* in_sizes, int n_in,
                              void* d_out, int out_size)
{
    (void)in_sizes; (void)n_in; (void)out_size;
    const float* x = (const float*)d_in[0];
    float* out = (float*)d_out;

    init_tables<<<2, 512>>>();

    const size_t shmem = 19200 * sizeof(float);   // 76800 B
    cudaFuncSetAttribute(stft_kernel,
                         cudaFuncAttributeMaxDynamicSharedMemorySize,
                         (int)shmem);

    dim3 grid(2048 / GROUP, NBATCH);   // (256, 32)
    stft_kernel<<<grid, THREADS, shmem>>>(x, out);
}

// round 4
// speedup vs baseline: 2.2307x; 1.0911x over previous
#include <cuda_runtime.h>
#include <math.h>

// Problem constants
#define NFFT     1024
#define HOP      256
#define SIGLEN   524288
#define NBATCH   32
#define GROUP    8            // output frames per CTA
#define NFRAMES  9            // FFT frames per CTA (GROUP+1)
#define NBINS    512          // output freq bins (k = 1..512)
#define THREADS  512
#define XBUFLEN  (GROUP*HOP + NFFT)   // 3072

// precomputed tables (filled by init kernel, double-precision accurate)
__device__ float2 g_tw[NFFT];    // exp(-2*pi*i*t/1024)
__device__ float  g_win[NFFT];   // periodic hann

__global__ void init_tables()
{
    int t = blockIdx.x * blockDim.x + threadIdx.x;
    if (t < NFFT) {
        double ang = -2.0 * 3.14159265358979323846 * (double)t / 1024.0;
        double s, c;
        sincos(ang, &s, &c);
        g_tw[t] = make_float2((float)c, (float)s);
        g_win[t] = (float)(0.5 * (1.0 - cos(2.0 * 3.14159265358979323846 * (double)t / 1024.0)));
    }
}

__device__ __forceinline__ float wrap_pi(float d) {
    const float INV2PI = 0.15915494309189535f;
    const float TWOPI  = 6.283185307179586f;
    return d - TWOPI * rintf(d * INV2PI);
}

__device__ __forceinline__ float2 cmul(float2 a, float2 b) {
    return make_float2(a.x * b.x - a.y * b.y, a.x * b.y + a.y * b.x);
}

__device__ __forceinline__ float2 shflx(float2 v, int m) {
    float px = __shfl_xor_sync(0xffffffffu, v.x, m);
    float py = __shfl_xor_sync(0xffffffffu, v.y, m);
    return make_float2(px, py);
}

// 32-point DIF FFT across the 32 lanes of a warp.
// Input: lane l holds x[l]. Output: lane l holds X[brev5(l)].
__device__ __forceinline__ float2 wfft32(float2 v, int lane,
                                         float2 t16, float2 t8, float2 t4)
{
    float2 p;
    p = shflx(v, 16);
    if (lane & 16) v = cmul(make_float2(p.x - v.x, p.y - v.y), t16);
    else           v = make_float2(v.x + p.x, v.y + p.y);

    p = shflx(v, 8);
    if (lane & 8)  v = cmul(make_float2(p.x - v.x, p.y - v.y), t8);
    else           v = make_float2(v.x + p.x, v.y + p.y);

    p = shflx(v, 4);
    if (lane & 4)  v = cmul(make_float2(p.x - v.x, p.y - v.y), t4);
    else           v = make_float2(v.x + p.x, v.y + p.y);

    p = shflx(v, 2);
    if (lane & 2) {
        float2 s = make_float2(p.x - v.x, p.y - v.y);
        v = (lane & 1) ? make_float2(s.y, -s.x) : s;  // *(-i) when j==1
    } else {
        v = make_float2(v.x + p.x, v.y + p.y);
    }

    p = shflx(v, 1);
    if (lane & 1)  v = make_float2(p.x - v.x, p.y - v.y);
    else           v = make_float2(v.x + p.x, v.y + p.y);
    return v;
}

// padded index: +1 float per 32 (conflict-free for stride-32 access)
__device__ __forceinline__ int P(int i) { return i + (i >> 5); }

extern __shared__ float smem_raw[];

__global__ __launch_bounds__(THREADS, 2)
void stft_kernel(const float* __restrict__ x, float* __restrict__ out)
{
    // ---- shared layout ----
    float* winP  = smem_raw;                 // 1056 (padded 1024)
    float* xbufP = winP + 1056;              // 3168 (padded 3072)
    float* Ysre  = xbufP + 3168;             // 32*33 = 1056
    float* Ysim  = Ysre + 1056;              // 1056
    float* Sre   = Ysim + 1056;              // 1056 (padded 1024)
    float* Sim   = Sre + 1056;               // 1056
    // total 8448 floats = 33792 B

    const int tid  = threadIdx.x;
    const int w    = tid >> 5;
    const int lane = tid & 31;
    const int grp  = blockIdx.x;   // 0..255
    const int b    = blockIdx.y;   // 0..31

    // ---- stage window into smem (coalesced) ----
    #pragma unroll
    for (int i = tid; i < NFFT; i += THREADS)
        winP[P(i)] = g_win[i];

    // ---- per-thread loop-invariant constants ----
    const float2 t16 = g_tw[(lane & 15) << 5];
    const float2 t8  = g_tw[(lane & 7)  << 6];
    const float2 t4  = g_tw[(lane & 3)  << 7];
    const int    kk  = (int)(__brev((unsigned)lane) >> 27);  // brev5(lane)

    const int b0 = 2 * w;       // column / row indices owned by this warp
    const int b1 = 2 * w + 1;
    const int n0 = (lane << 5) + b0;
    const int n1 = (lane << 5) + b1;

    // step-2 twiddles W1024^(b*k1) are invariant across the 5 FFTs
    const float2 twA = g_tw[b0 * kk];
    const float2 twB = g_tw[b1 * kk];

    // ---- load input window with reflect padding ----
    {
        const long base = (long)grp * (GROUP * HOP) - (NFFT / 2);
        const float* xb = x + (long)b * SIGLEN;
        #pragma unroll
        for (int i = tid; i < XBUFLEN; i += THREADS) {
            long p = base + i;
            if (p < 0) p = -p;
            else if (p >= SIGLEN) p = 2L * (SIGLEN - 1) - p;
            xbufP[P(i)] = xb[p];
        }
    }
    __syncthreads();

    // window values are loop-invariant per thread
    const float w0v = winP[P(n0)];
    const float w1v = winP[P(n1)];

    // register accumulators for this thread's frequency row f = tid
    float m[GROUP];      // log-magnitude per output time
    float d[GROUP];      // wrapped phase diff per output time
    float prevPh = 0.0f;

    // ---- 5 complex FFTs covering 9 real frames (pairs packed in re/im) ----
    #pragma unroll
    for (int pr = 0; pr < 5; pr++) {
        const int gA = 2 * pr;
        const int gB = 2 * pr + 1;
        const bool hasB = (gB < NFRAMES);

        // ===== step 1: 32-pt FFT over lane dim for columns b0, b1 =====
        {
            float2 v0, v1;
            v0.x = w0v * xbufP[P(gA * HOP + n0)];
            v1.x = w1v * xbufP[P(gA * HOP + n1)];
            if (hasB) {
                v0.y = w0v * xbufP[P(gB * HOP + n0)];
                v1.y = w1v * xbufP[P(gB * HOP + n1)];
            } else {
                v0.y = 0.0f; v1.y = 0.0f;
            }

            v0 = wfft32(v0, lane, t16, t8, t4);   // Y[k1=kk, b0]
            v1 = wfft32(v1, lane, t16, t8, t4);   // Y[k1=kk, b1]

            // ===== step 2: twiddle =====
            v0 = cmul(v0, twA);
            v1 = cmul(v1, twB);

            // transpose store (conflict-free: bank = (kk + b)%32)
            Ysre[kk * 33 + b0] = v0.x;  Ysim[kk * 33 + b0] = v0.y;
            Ysre[kk * 33 + b1] = v1.x;  Ysim[kk * 33 + b1] = v1.y;
        }
        __syncthreads();   // Ys write -> Ys read

        // ===== step 3: 32-pt FFT over b for rows k1 = b0, b1 =====
        {
            float2 u0 = make_float2(Ysre[b0 * 33 + lane], Ysim[b0 * 33 + lane]);
            float2 u1 = make_float2(Ysre[b1 * 33 + lane], Ysim[b1 * 33 + lane]);
            u0 = wfft32(u0, lane, t16, t8, t4);   // X[b0 + 32*kk]
            u1 = wfft32(u1, lane, t16, t8, t4);   // X[b1 + 32*kk]
            const int k0  = b0 + (kk << 5);
            const int k1i = b1 + (kk << 5);
            Sre[P(k0)]  = u0.x;  Sim[P(k0)]  = u0.y;
            Sre[P(k1i)] = u1.x;  Sim[P(k1i)] = u1.y;
        }
        __syncthreads();   // S write -> S read (also orders Ys read before next Ys write)

        // ===== unpack packed real spectra; k = tid+1 (skip DC) =====
        {
            const int k = tid + 1;
            const int r = NFFT - k;
            const float zkr = Sre[P(k)], zki = Sim[P(k)];
            const float zrr = Sre[P(r)], zri = Sim[P(r)];
            // A = spectrum of frame gA
            const float Are = 0.5f * (zkr + zrr);
            const float Aim = 0.5f * (zki - zri);
            const float phA = atan2f(Aim, Are);
            if (pr > 0) {
                d[gA - 1] = wrap_pi(phA - prevPh);
                const float m2 = Are * Are + Aim * Aim;
                m[gA - 1] = (0.5f * logf(fmaxf(m2, 1e-14f)) + 17.0f) * (1.0f / 23.0f);
            }
            if (hasB) {
                // B = spectrum of frame gB
                const float Bre = 0.5f * (zki + zri);
                const float Bim = 0.5f * (zrr - zkr);
                const float phB = atan2f(Bim, Bre);
                d[gB - 1] = wrap_pi(phB - phA);
                const float m2 = Bre * Bre + Bim * Bim;
                m[gB - 1] = (0.5f * logf(fmaxf(m2, 1e-14f)) + 17.0f) * (1.0f / 23.0f);
                prevPh = phB;
            }
        }
        // no sync needed here: next iter's first sync orders S/Ys reuse
    }

    // ---- writeout from registers: thread tid owns freq row f = tid ----
    {
        const long t0 = (long)grp * GROUP;
        float* o0 = out + ((((long)b * 2 + 0) * 512 + tid) * 2048 + t0);
        float* o1 = out + ((((long)b * 2 + 1) * 512 + tid) * 2048 + t0);
        ((float4*)o0)[0] = make_float4(m[0], m[1], m[2], m[3]);
        ((float4*)o0)[1] = make_float4(m[4], m[5], m[6], m[7]);
        ((float4*)o1)[0] = make_float4(d[0], d[1], d[2], d[3]);
        ((float4*)o1)[1] = make_float4(d[4], d[5], d[6], d[7]);
    }
}

extern "C" void kernel_launch(void* const* d_in, const int* in_sizes, int n_in,
                              void* d_out, int out_size)
{
    (void)in_sizes; (void)n_in; (void)out_size;
    const float* x = (const float*)d_in[0];
    float* out = (float*)d_out;

    init_tables<<<2, 512>>>();

    const size_t shmem = 8448 * sizeof(float);   // 33792 B
    cudaFuncSetAttribute(stft_kernel,
                         cudaFuncAttributeMaxDynamicSharedMemorySize,
                         (int)shmem);

    dim3 grid(2048 / GROUP, NBATCH);   // (256, 32)
    stft_kernel<<<grid, THREADS, shmem>>>(x, out);
}